// round 7
// baseline (speedup 1.0000x reference)
#include <cuda_runtime.h>
#include <cuda_bf16.h>
#include <cstdint>

// Problem constants (Head_84533546320520)
#define BATCH 8
#define SEQ   2048
#define DEMB  1024
#define HEAD  64
#define NROWS (BATCH * SEQ)   // 16384
#define SCALE 0.125f          // HEAD^-0.5
#define KSPLIT 2

// Pre-split bf16 hi/lo scratch for projected q/k/v (q pre-scaled by SCALE).
__device__ __nv_bfloat16 g_qh[NROWS * HEAD];
__device__ __nv_bfloat16 g_ql[NROWS * HEAD];
__device__ __nv_bfloat16 g_kh[NROWS * HEAD];
__device__ __nv_bfloat16 g_kl[NROWS * HEAD];
__device__ __nv_bfloat16 g_vh[NROWS * HEAD];
__device__ __nv_bfloat16 g_vl[NROWS * HEAD];

// Split-K partials: unnormalized O + per-row (m, l)
__device__ float g_po[KSPLIT][NROWS * HEAD];
__device__ float g_pm[KSPLIT][NROWS];
__device__ float g_pl[KSPLIT][NROWS];

// ===========================================================================
// mma.sync / cp.async helpers
// ===========================================================================
__device__ __forceinline__ uint32_t smem_to_u32(const void* p) {
    uint32_t a;
    asm("{ .reg .u64 t; cvta.to.shared.u64 t, %1; cvt.u32.u64 %0, t; }"
        : "=r"(a) : "l"(p));
    return a;
}
__device__ __forceinline__ void ldsm_x4(uint32_t* r, uint32_t addr) {
    asm volatile("ldmatrix.sync.aligned.m8n8.x4.shared.b16 {%0,%1,%2,%3}, [%4];"
        : "=r"(r[0]), "=r"(r[1]), "=r"(r[2]), "=r"(r[3]) : "r"(addr));
}
__device__ __forceinline__ void ldsm_x4_trans(uint32_t* r, uint32_t addr) {
    asm volatile("ldmatrix.sync.aligned.m8n8.x4.trans.shared.b16 {%0,%1,%2,%3}, [%4];"
        : "=r"(r[0]), "=r"(r[1]), "=r"(r[2]), "=r"(r[3]) : "r"(addr));
}
__device__ __forceinline__ void mma_bf16(float* d, const uint32_t* a, const uint32_t* b) {
    asm volatile(
        "mma.sync.aligned.m16n8k16.row.col.f32.bf16.bf16.f32 "
        "{%0,%1,%2,%3}, {%4,%5,%6,%7}, {%8,%9}, {%0,%1,%2,%3};"
        : "+f"(d[0]), "+f"(d[1]), "+f"(d[2]), "+f"(d[3])
        : "r"(a[0]), "r"(a[1]), "r"(a[2]), "r"(a[3]), "r"(b[0]), "r"(b[1]));
}
__device__ __forceinline__ void split2(float x, float y, uint32_t& h, uint32_t& l) {
    __nv_bfloat162 hb = __float22bfloat162_rn(make_float2(x, y));
    float2 hf = __bfloat1622float2(hb);
    __nv_bfloat162 lb = __float22bfloat162_rn(make_float2(x - hf.x, y - hf.y));
    h = *reinterpret_cast<uint32_t*>(&hb);
    l = *reinterpret_cast<uint32_t*>(&lb);
}
__device__ __forceinline__ void cp_async16(uint32_t saddr, const void* gaddr) {
    asm volatile("cp.async.cg.shared.global [%0], [%1], 16;"
        :: "r"(saddr), "l"(gaddr) : "memory");
}
#define CP_COMMIT()  asm volatile("cp.async.commit_group;" ::: "memory")
#define CP_WAIT(n)   asm volatile("cp.async.wait_group %0;" :: "n"(n) : "memory")

// ===========================================================================
// Kernel 1: projections (UNCHANGED, validated). Stores split bf16 hi/lo.
// ===========================================================================
#define KC 64
#define NCH (DEMB / KC)
#define APAD 72
#define PROJ_SMEM ((2 * 128 * APAD + 2 * 64 * APAD) * 2)

__global__ __launch_bounds__(256) void proj_mma_kernel(
    const float* __restrict__ q, const float* __restrict__ k,
    const float* __restrict__ v,
    const float* __restrict__ Wq, const float* __restrict__ Wk,
    const float* __restrict__ Wv)
{
    extern __shared__ __align__(16) __nv_bfloat16 smb[];
    __nv_bfloat16* AsHi = smb;
    __nv_bfloat16* AsLo = AsHi + 128 * APAD;
    __nv_bfloat16* BsHi = AsLo + 128 * APAD;
    __nv_bfloat16* BsLo = BsHi + 64 * APAD;
    const uint32_t aHiB = smem_to_u32(AsHi);
    const uint32_t aLoB = smem_to_u32(AsLo);
    const uint32_t bHiB = smem_to_u32(BsHi);
    const uint32_t bLoB = smem_to_u32(BsLo);

    const int which = blockIdx.y;
    const float* __restrict__ X = (which == 0) ? q : (which == 1) ? k : v;
    const float* __restrict__ W = (which == 0) ? Wq : (which == 1) ? Wk : Wv;
    __nv_bfloat16* __restrict__ outH = (which == 0) ? g_qh : (which == 1) ? g_kh : g_vh;
    __nv_bfloat16* __restrict__ outL = (which == 0) ? g_ql : (which == 1) ? g_kl : g_vl;
    const float postmul = (which == 0) ? SCALE : 1.0f;

    const int tid = threadIdx.x;
    const int wid = tid >> 5;
    const int lane = tid & 31;
    const int l16 = lane & 15;
    const int hi8 = (lane >> 4) << 3;
    const int row0 = blockIdx.x * 128;
    const int m0 = wid * 16;

    float acc[8][4] = {};

    for (int c = 0; c < NCH; c++) {
        const int k0 = c * KC;
        if (c > 0) __syncthreads();

        #pragma unroll
        for (int i = 0; i < 8; i++) {
            int idx = tid + i * 256;
            int r   = idx >> 4;
            int cg  = idx & 15;
            float4 t = *reinterpret_cast<const float4*>(
                X + (size_t)(row0 + r) * DEMB + k0 + cg * 4);
            __nv_bfloat162 h01 = __float22bfloat162_rn(make_float2(t.x, t.y));
            __nv_bfloat162 h23 = __float22bfloat162_rn(make_float2(t.z, t.w));
            float2 f01 = __bfloat1622float2(h01);
            float2 f23 = __bfloat1622float2(h23);
            __nv_bfloat162 l01 = __float22bfloat162_rn(make_float2(t.x - f01.x, t.y - f01.y));
            __nv_bfloat162 l23 = __float22bfloat162_rn(make_float2(t.z - f23.x, t.w - f23.y));
            int o = r * APAD + cg * 4;
            *reinterpret_cast<__nv_bfloat162*>(&AsHi[o])     = h01;
            *reinterpret_cast<__nv_bfloat162*>(&AsHi[o + 2]) = h23;
            *reinterpret_cast<__nv_bfloat162*>(&AsLo[o])     = l01;
            *reinterpret_cast<__nv_bfloat162*>(&AsLo[o + 2]) = l23;
        }
        #pragma unroll
        for (int i = 0; i < 4; i++) {
            int idx = tid + i * 256;
            int kk  = idx >> 4;
            int ng  = idx & 15;
            float4 t = *reinterpret_cast<const float4*>(
                W + (size_t)(k0 + kk) * HEAD + ng * 4);
            __nv_bfloat162 h01 = __float22bfloat162_rn(make_float2(t.x, t.y));
            __nv_bfloat162 h23 = __float22bfloat162_rn(make_float2(t.z, t.w));
            float2 f01 = __bfloat1622float2(h01);
            float2 f23 = __bfloat1622float2(h23);
            __nv_bfloat162 l01 = __float22bfloat162_rn(make_float2(t.x - f01.x, t.y - f01.y));
            __nv_bfloat162 l23 = __float22bfloat162_rn(make_float2(t.z - f23.x, t.w - f23.y));
            int o = kk * APAD + ng * 4;
            *reinterpret_cast<__nv_bfloat162*>(&BsHi[o])     = h01;
            *reinterpret_cast<__nv_bfloat162*>(&BsHi[o + 2]) = h23;
            *reinterpret_cast<__nv_bfloat162*>(&BsLo[o])     = l01;
            *reinterpret_cast<__nv_bfloat162*>(&BsLo[o + 2]) = l23;
        }
        __syncthreads();

        #pragma unroll
        for (int kk = 0; kk < 4; kk++) {
            uint32_t a_hi[4], a_lo[4];
            uint32_t aoff = (uint32_t)(((m0 + l16) * APAD + kk * 16 + hi8) * 2);
            ldsm_x4(a_hi, aHiB + aoff);
            ldsm_x4(a_lo, aLoB + aoff);
            #pragma unroll
            for (int nb = 0; nb < 4; nb++) {
                uint32_t bh[4], bl[4];
                uint32_t boff = (uint32_t)(((kk * 16 + l16) * APAD + nb * 16 + hi8) * 2);
                ldsm_x4_trans(bh, bHiB + boff);
                ldsm_x4_trans(bl, bLoB + boff);
                mma_bf16(acc[2 * nb + 0], a_hi, bh + 0);
                mma_bf16(acc[2 * nb + 1], a_hi, bh + 2);
                mma_bf16(acc[2 * nb + 0], a_hi, bl + 0);
                mma_bf16(acc[2 * nb + 1], a_hi, bl + 2);
                mma_bf16(acc[2 * nb + 0], a_lo, bh + 0);
                mma_bf16(acc[2 * nb + 1], a_lo, bh + 2);
            }
        }
    }

    const int r = lane >> 2;
    const int cc = (lane & 3) * 2;
    const size_t rA = (size_t)(row0 + m0 + r) * HEAD;
    const size_t rB = (size_t)(row0 + m0 + r + 8) * HEAD;
    #pragma unroll
    for (int j = 0; j < 8; j++) {
        uint32_t h, l;
        split2(acc[j][0] * postmul, acc[j][1] * postmul, h, l);
        *reinterpret_cast<uint32_t*>(&outH[rA + j * 8 + cc]) = h;
        *reinterpret_cast<uint32_t*>(&outL[rA + j * 8 + cc]) = l;
        split2(acc[j][2] * postmul, acc[j][3] * postmul, h, l);
        *reinterpret_cast<uint32_t*>(&outH[rB + j * 8 + cc]) = h;
        *reinterpret_cast<uint32_t*>(&outL[rB + j * 8 + cc]) = l;
    }
}

// ===========================================================================
// Kernel 2: split-K flash attention. grid = (SEQ/64, BATCH, KSPLIT).
// CTA z handles k-tiles [z*16, z*16+16); writes UNNORMALIZED O + (m, l).
// ===========================================================================
#define AP 72
#define BUFB (64 * AP * 2)
#define STAGEB (4 * BUFB)
#define ATTN_SMEM (2 * STAGEB + 256)
#define NT (SEQ / 64)               // 32
#define NTH (NT / KSPLIT)           // 16

__global__ __launch_bounds__(128) void attn_mma_kernel(
    const int* __restrict__ mask)
{
    extern __shared__ __align__(16) char smc[];
    const uint32_t smemB = smem_to_u32(smc);
    float* biasS = reinterpret_cast<float*>(smc + 2 * STAGEB);

    const int b  = blockIdx.y;
    const int q0 = blockIdx.x * 64;
    const int z  = blockIdx.z;
    const int kbase = z * NTH * 64;
    const size_t base = (size_t)b * SEQ * HEAD;

    const int tid  = threadIdx.x;
    const int wid  = tid >> 5;
    const int lane = tid & 31;
    const int l16  = lane & 15;
    const int hi8  = (lane >> 4) << 3;
    const int m0w  = wid * 16;
    const int c2   = (lane & 3) * 2;

    const int krow = (lane & 7) + ((lane & 16) >> 1);
    const int hcol = (lane & 8);

    // ---- stage pre-split Q into stage-0 smem, extract A-frags ----
    #pragma unroll
    for (int i = 0; i < 4; i++) {
        int idx = tid + i * 128;
        int r = idx >> 3, cq = idx & 7;
        uint4 th = *reinterpret_cast<const uint4*>(g_qh + base + (size_t)(q0 + r) * HEAD + cq * 8);
        uint4 tl = *reinterpret_cast<const uint4*>(g_ql + base + (size_t)(q0 + r) * HEAD + cq * 8);
        *reinterpret_cast<uint4*>(smc + r * 144 + cq * 16)        = th;
        *reinterpret_cast<uint4*>(smc + BUFB + r * 144 + cq * 16) = tl;
    }
    __syncthreads();
    uint32_t qh[4][4], qlr[4][4];
    #pragma unroll
    for (int kh = 0; kh < 4; kh++) {
        uint32_t aoff = (uint32_t)(((m0w + l16) * AP + kh * 16 + hi8) * 2);
        ldsm_x4(qh[kh],  smemB + aoff);
        ldsm_x4(qlr[kh], smemB + BUFB + aoff);
    }
    __syncthreads();

    // ---- prefetch first tile ----
    const __nv_bfloat16* srcs[4] = {g_kh + base, g_kl + base, g_vh + base, g_vl + base};
    {
        #pragma unroll
        for (int i = 0; i < 16; i++) {
            const int buf = i >> 2;
            int rem = tid + (i & 3) * 128;
            int r = rem >> 3, cq = rem & 7;
            cp_async16(smemB + buf * BUFB + r * 144 + cq * 16,
                       srcs[buf] + (size_t)(kbase + r) * HEAD + cq * 8);
        }
        CP_COMMIT();
    }

    const float NEG_INF = __int_as_float(0xff800000);
    float mR0 = NEG_INF, mR1 = NEG_INF, lS0 = 0.f, lS1 = 0.f;
    float o[8][4] = {};

    for (int kt = 0; kt < NTH; kt++) {
        const int s = kt & 1;
        const uint32_t stB = smemB + s * STAGEB;
        const int ktile = kbase + kt * 64;

        if (kt + 1 < NTH) {
            const int k1 = ktile + 64;
            const uint32_t st2 = smemB + ((kt + 1) & 1) * STAGEB;
            #pragma unroll
            for (int i = 0; i < 16; i++) {
                const int buf = i >> 2;
                int rem = tid + (i & 3) * 128;
                int r = rem >> 3, cq = rem & 7;
                cp_async16(st2 + buf * BUFB + r * 144 + cq * 16,
                           srcs[buf] + (size_t)(k1 + r) * HEAD + cq * 8);
            }
            CP_COMMIT();
            CP_WAIT(1);
        } else {
            CP_WAIT(0);
        }
        if (tid < 64)
            biasS[tid] = (mask[(size_t)b * SEQ + ktile + tid] != 0) ? 0.f : -1e30f;
        __syncthreads();

        // ---- S = Q @ K^T ----
        float sF[8][4] = {};
        #pragma unroll
        for (int kh = 0; kh < 4; kh++) {
            #pragma unroll
            for (int nb = 0; nb < 4; nb++) {
                uint32_t bh[4], bl[4];
                uint32_t boff = (uint32_t)(((nb * 16 + krow) * AP + kh * 16 + hcol) * 2);
                ldsm_x4(bh, stB + boff);
                ldsm_x4(bl, stB + BUFB + boff);
                mma_bf16(sF[2 * nb],     qh[kh],  bh);
                mma_bf16(sF[2 * nb + 1], qh[kh],  bh + 2);
                mma_bf16(sF[2 * nb],     qh[kh],  bl);
                mma_bf16(sF[2 * nb + 1], qh[kh],  bl + 2);
                mma_bf16(sF[2 * nb],     qlr[kh], bh);
                mma_bf16(sF[2 * nb + 1], qlr[kh], bh + 2);
            }
        }

        // ---- online softmax ----
        float mx0 = NEG_INF, mx1 = NEG_INF;
        #pragma unroll
        for (int j = 0; j < 8; j++) {
            float2 bv = *reinterpret_cast<float2*>(&biasS[j * 8 + c2]);
            sF[j][0] += bv.x; sF[j][1] += bv.y; sF[j][2] += bv.x; sF[j][3] += bv.y;
            mx0 = fmaxf(mx0, fmaxf(sF[j][0], sF[j][1]));
            mx1 = fmaxf(mx1, fmaxf(sF[j][2], sF[j][3]));
        }
        mx0 = fmaxf(mx0, __shfl_xor_sync(0xffffffffu, mx0, 1));
        mx0 = fmaxf(mx0, __shfl_xor_sync(0xffffffffu, mx0, 2));
        mx1 = fmaxf(mx1, __shfl_xor_sync(0xffffffffu, mx1, 1));
        mx1 = fmaxf(mx1, __shfl_xor_sync(0xffffffffu, mx1, 2));
        float mn0 = fmaxf(mR0, mx0), mn1 = fmaxf(mR1, mx1);
        float a0 = __expf(mR0 - mn0), a1 = __expf(mR1 - mn1);
        float sm0 = 0.f, sm1 = 0.f;
        #pragma unroll
        for (int j = 0; j < 8; j++) {
            sF[j][0] = __expf(sF[j][0] - mn0);
            sF[j][1] = __expf(sF[j][1] - mn0);
            sF[j][2] = __expf(sF[j][2] - mn1);
            sF[j][3] = __expf(sF[j][3] - mn1);
            sm0 += sF[j][0] + sF[j][1];
            sm1 += sF[j][2] + sF[j][3];
        }
        sm0 += __shfl_xor_sync(0xffffffffu, sm0, 1);
        sm0 += __shfl_xor_sync(0xffffffffu, sm0, 2);
        sm1 += __shfl_xor_sync(0xffffffffu, sm1, 1);
        sm1 += __shfl_xor_sync(0xffffffffu, sm1, 2);
        lS0 = lS0 * a0 + sm0; lS1 = lS1 * a1 + sm1;
        mR0 = mn0; mR1 = mn1;
        #pragma unroll
        for (int j = 0; j < 8; j++) {
            o[j][0] *= a0; o[j][1] *= a0; o[j][2] *= a1; o[j][3] *= a1;
        }

        // ---- O += P @ V ----
        #pragma unroll
        for (int kb = 0; kb < 4; kb++) {
            uint32_t ah[4], al[4];
            split2(sF[2 * kb][0],     sF[2 * kb][1],     ah[0], al[0]);
            split2(sF[2 * kb][2],     sF[2 * kb][3],     ah[1], al[1]);
            split2(sF[2 * kb + 1][0], sF[2 * kb + 1][1], ah[2], al[2]);
            split2(sF[2 * kb + 1][2], sF[2 * kb + 1][3], ah[3], al[3]);
            #pragma unroll
            for (int nb = 0; nb < 4; nb++) {
                uint32_t vh[4], vl[4];
                uint32_t boff = (uint32_t)(((kb * 16 + l16) * AP + nb * 16 + hi8) * 2);
                ldsm_x4_trans(vh, stB + 2 * BUFB + boff);
                ldsm_x4_trans(vl, stB + 3 * BUFB + boff);
                mma_bf16(o[2 * nb],     ah, vh);
                mma_bf16(o[2 * nb + 1], ah, vh + 2);
                mma_bf16(o[2 * nb],     ah, vl);
                mma_bf16(o[2 * nb + 1], ah, vl + 2);
                mma_bf16(o[2 * nb],     al, vh);
                mma_bf16(o[2 * nb + 1], al, vh + 2);
            }
        }
        __syncthreads();
    }

    // ---- store UNNORMALIZED partials + (m, l) ----
    const int rA = b * SEQ + q0 + m0w + (lane >> 2);
    float* po = g_po[z];
    #pragma unroll
    for (int j = 0; j < 8; j++) {
        *reinterpret_cast<float2*>(po + (size_t)rA * HEAD + j * 8 + c2) =
            make_float2(o[j][0], o[j][1]);
        *reinterpret_cast<float2*>(po + (size_t)(rA + 8) * HEAD + j * 8 + c2) =
            make_float2(o[j][2], o[j][3]);
    }
    if ((lane & 3) == 0) {
        g_pm[z][rA] = mR0;     g_pl[z][rA] = lS0;
        g_pm[z][rA + 8] = mR1; g_pl[z][rA + 8] = lS1;
    }
}

// ===========================================================================
// Kernel 3: combine split-K partials. 1 float4 per thread.
// ===========================================================================
__global__ __launch_bounds__(256) void combine_kernel(float* __restrict__ out)
{
    int idx = blockIdx.x * 256 + threadIdx.x;     // float4 index
    int row = idx >> 4;                            // (idx*4)/HEAD
    float m0 = g_pm[0][row], m1 = g_pm[1][row];
    float l0 = g_pl[0][row], l1 = g_pl[1][row];
    float M = fmaxf(m0, m1);
    float w0 = __expf(m0 - M), w1 = __expf(m1 - M);
    float inv = 1.0f / (w0 * l0 + w1 * l1);
    float4 a = reinterpret_cast<const float4*>(g_po[0])[idx];
    float4 c = reinterpret_cast<const float4*>(g_po[1])[idx];
    float4 r;
    r.x = (w0 * a.x + w1 * c.x) * inv;
    r.y = (w0 * a.y + w1 * c.y) * inv;
    r.z = (w0 * a.z + w1 * c.z) * inv;
    r.w = (w0 * a.w + w1 * c.w) * inv;
    reinterpret_cast<float4*>(out)[idx] = r;
}

// ---------------------------------------------------------------------------
extern "C" void kernel_launch(void* const* d_in, const int* in_sizes, int n_in,
                              void* d_out, int out_size)
{
    const void* big[3]   = {0, 0, 0};
    const void* small[3] = {0, 0, 0};
    const void* mk = 0;
    int nb = 0, ns = 0;
    for (int i = 0; i < n_in; i++) {
        if (in_sizes[i] == NROWS * DEMB)      { if (nb < 3) big[nb++] = d_in[i]; }
        else if (in_sizes[i] == DEMB * HEAD)  { if (ns < 3) small[ns++] = d_in[i]; }
        else if (in_sizes[i] == BATCH * SEQ)  { mk = d_in[i]; }
    }
    const float* q  = (const float*)big[0];
    const float* k  = (const float*)big[1];
    const float* v  = (const float*)big[2];
    const float* Wq = (const float*)small[0];
    const float* Wk = (const float*)small[1];
    const float* Wv = (const float*)small[2];
    const int*   mask = (const int*)mk;
    float* out = (float*)d_out;

    static bool attr_set = false;
    if (!attr_set) {
        cudaFuncSetAttribute(proj_mma_kernel, cudaFuncAttributeMaxDynamicSharedMemorySize, PROJ_SMEM);
        cudaFuncSetAttribute(attn_mma_kernel, cudaFuncAttributeMaxDynamicSharedMemorySize, ATTN_SMEM);
        attr_set = true;
    }

    proj_mma_kernel<<<dim3(NROWS / 128, 3), 256, PROJ_SMEM>>>(q, k, v, Wq, Wk, Wv);
    attn_mma_kernel<<<dim3(SEQ / 64, BATCH, KSPLIT), 128, ATTN_SMEM>>>(mask);
    combine_kernel<<<(NROWS * HEAD / 4) / 256, 256>>>(out);
}

// round 8
// speedup vs baseline: 1.0190x; 1.0190x over previous
#include <cuda_runtime.h>
#include <cuda_bf16.h>
#include <cstdint>

// Problem constants (Head_84533546320520)
#define BATCH 8
#define SEQ   2048
#define DEMB  1024
#define HEAD  64
#define NROWS (BATCH * SEQ)   // 16384
#define SCALE 0.125f          // HEAD^-0.5

// Pre-split bf16 hi/lo scratch for projected q/k/v (q pre-scaled by SCALE).
__device__ __nv_bfloat16 g_qh[NROWS * HEAD];
__device__ __nv_bfloat16 g_ql[NROWS * HEAD];
__device__ __nv_bfloat16 g_kh[NROWS * HEAD];
__device__ __nv_bfloat16 g_kl[NROWS * HEAD];
__device__ __nv_bfloat16 g_vh[NROWS * HEAD];
__device__ __nv_bfloat16 g_vl[NROWS * HEAD];

// Pre-split weights: [which][k*HEAD + n]
__device__ __nv_bfloat16 g_wh[3][DEMB * HEAD];
__device__ __nv_bfloat16 g_wl[3][DEMB * HEAD];

// ===========================================================================
// helpers
// ===========================================================================
__device__ __forceinline__ uint32_t smem_to_u32(const void* p) {
    uint32_t a;
    asm("{ .reg .u64 t; cvta.to.shared.u64 t, %1; cvt.u32.u64 %0, t; }"
        : "=r"(a) : "l"(p));
    return a;
}
__device__ __forceinline__ void ldsm_x4(uint32_t* r, uint32_t addr) {
    asm volatile("ldmatrix.sync.aligned.m8n8.x4.shared.b16 {%0,%1,%2,%3}, [%4];"
        : "=r"(r[0]), "=r"(r[1]), "=r"(r[2]), "=r"(r[3]) : "r"(addr));
}
__device__ __forceinline__ void ldsm_x4_trans(uint32_t* r, uint32_t addr) {
    asm volatile("ldmatrix.sync.aligned.m8n8.x4.trans.shared.b16 {%0,%1,%2,%3}, [%4];"
        : "=r"(r[0]), "=r"(r[1]), "=r"(r[2]), "=r"(r[3]) : "r"(addr));
}
__device__ __forceinline__ void mma_bf16(float* d, const uint32_t* a, const uint32_t* b) {
    asm volatile(
        "mma.sync.aligned.m16n8k16.row.col.f32.bf16.bf16.f32 "
        "{%0,%1,%2,%3}, {%4,%5,%6,%7}, {%8,%9}, {%0,%1,%2,%3};"
        : "+f"(d[0]), "+f"(d[1]), "+f"(d[2]), "+f"(d[3])
        : "r"(a[0]), "r"(a[1]), "r"(a[2]), "r"(a[3]), "r"(b[0]), "r"(b[1]));
}
__device__ __forceinline__ void split2(float x, float y, uint32_t& h, uint32_t& l) {
    __nv_bfloat162 hb = __float22bfloat162_rn(make_float2(x, y));
    float2 hf = __bfloat1622float2(hb);
    __nv_bfloat162 lb = __float22bfloat162_rn(make_float2(x - hf.x, y - hf.y));
    h = *reinterpret_cast<uint32_t*>(&hb);
    l = *reinterpret_cast<uint32_t*>(&lb);
}
__device__ __forceinline__ void cp_async16(uint32_t saddr, const void* gaddr) {
    asm volatile("cp.async.cg.shared.global [%0], [%1], 16;"
        :: "r"(saddr), "l"(gaddr) : "memory");
}
#define CP_COMMIT()  asm volatile("cp.async.commit_group;" ::: "memory")
#define CP_WAIT(n)   asm volatile("cp.async.wait_group %0;" :: "n"(n) : "memory")

// ===========================================================================
// Kernel 0: pre-split W into bf16 hi/lo. grid (64, 3), block 256.
// ===========================================================================
__global__ __launch_bounds__(256) void wsplit_kernel(
    const float* __restrict__ Wq, const float* __restrict__ Wk,
    const float* __restrict__ Wv)
{
    const int which = blockIdx.y;
    const float* __restrict__ W = (which == 0) ? Wq : (which == 1) ? Wk : Wv;
    int idx = blockIdx.x * 256 + threadIdx.x;       // float4 index, 16384 total
    float4 t = reinterpret_cast<const float4*>(W)[idx];
    uint32_t h0, l0, h1, l1;
    split2(t.x, t.y, h0, l0);
    split2(t.z, t.w, h1, l1);
    uint2 hv = make_uint2(h0, h1), lv = make_uint2(l0, l1);
    *reinterpret_cast<uint2*>(&g_wh[which][idx * 4]) = hv;
    *reinterpret_cast<uint2*>(&g_wl[which][idx * 4]) = lv;
}

// ===========================================================================
// Kernel 1: projections, software-pipelined.
// grid = (NROWS/128, 3), block = 256 (8 warps).
// Per chunk: convert A-regs(c)->smem; LDG A-regs(c+1); cp.async B(c+1);
// MMA(c). Double-buffered A and B bf16 tiles.
// ===========================================================================
#define KC 64
#define NCH (DEMB / KC)
#define APAD 72
#define ABUF (128 * APAD * 2)    // 18432 B (one hi or lo buffer)
#define BBUF (64 * APAD * 2)     // 9216 B
#define PROJ_SMEM (4 * ABUF + 4 * BBUF)   // 110592 B

__global__ __launch_bounds__(256) void proj_mma_kernel(
    const float* __restrict__ q, const float* __restrict__ k,
    const float* __restrict__ v)
{
    extern __shared__ __align__(16) char smc[];
    const uint32_t base = smem_to_u32(smc);
    // A stage s: hi at base + s*2*ABUF, lo at +ABUF
    // B stage s: hi at base + 4*ABUF + s*2*BBUF, lo at +BBUF
    const uint32_t bBase = base + 4 * ABUF;

    const int which = blockIdx.y;
    const float* __restrict__ X = (which == 0) ? q : (which == 1) ? k : v;
    const __nv_bfloat16* __restrict__ Wh = g_wh[which];
    const __nv_bfloat16* __restrict__ Wl = g_wl[which];
    __nv_bfloat16* __restrict__ outH = (which == 0) ? g_qh : (which == 1) ? g_kh : g_vh;
    __nv_bfloat16* __restrict__ outL = (which == 0) ? g_ql : (which == 1) ? g_kl : g_vl;
    const float postmul = (which == 0) ? SCALE : 1.0f;

    const int tid = threadIdx.x;
    const int wid = tid >> 5;
    const int lane = tid & 31;
    const int l16 = lane & 15;
    const int hi8 = (lane >> 4) << 3;
    const int row0 = blockIdx.x * 128;
    const int m0 = wid * 16;

    // per-thread A-row/col for LDG + convert
    const int ar = tid >> 1;                 // 0..127 (row)
    const int ac8 = (tid & 1) * 8;           // col group: 8 floats

    float4 aR[2][4];   // chunk's X data: 2 float4 per 8-col group? -> [g][2]
    // layout: thread handles rows ar, cols [ac8*4? ] -- redefine:
    // Each thread: 8 float4 = rows? Use original mapping: idx=tid+i*256,
    // r=idx>>4, cg=idx&15. Keep regs aR8[8].
    float4 aR8[8];

    auto loadA = [&](int k0) {
        #pragma unroll
        for (int i = 0; i < 8; i++) {
            int idx = tid + i * 256;
            int r = idx >> 4, cg = idx & 15;
            aR8[i] = *reinterpret_cast<const float4*>(
                X + (size_t)(row0 + r) * DEMB + k0 + cg * 4);
        }
    };
    auto convA = [&](int s) {
        const uint32_t aHi = base + s * 2 * ABUF;
        const uint32_t aLo = aHi + ABUF;
        #pragma unroll
        for (int i = 0; i < 8; i++) {
            int idx = tid + i * 256;
            int r = idx >> 4, cg = idx & 15;
            float4 t = aR8[i];
            uint32_t h0, l0, h1, l1;
            split2(t.x, t.y, h0, l0);
            split2(t.z, t.w, h1, l1);
            uint32_t off = (uint32_t)(r * APAD + cg * 4) * 2;
            asm volatile("st.shared.v2.b32 [%0], {%1, %2};" :: "r"(aHi + off), "r"(h0), "r"(h1) : "memory");
            asm volatile("st.shared.v2.b32 [%0], {%1, %2};" :: "r"(aLo + off), "r"(l0), "r"(l1) : "memory");
        }
    };
    auto cpB = [&](int c, int s) {
        const uint32_t bHi = bBase + s * 2 * BBUF;
        const uint32_t bLo = bHi + BBUF;
        const int k0 = c * KC;
        #pragma unroll
        for (int i = 0; i < 4; i++) {
            int rem = tid + (i & 1) * 256;     // 0..511
            int r = rem >> 3, cq = rem & 7;
            uint32_t dst = ((i >> 1) ? bLo : bHi) + r * 144 + cq * 16;
            const __nv_bfloat16* src = ((i >> 1) ? Wl : Wh) + (size_t)(k0 + r) * HEAD + cq * 8;
            cp_async16(dst, src);
        }
        CP_COMMIT();
    };

    float acc[8][4] = {};

    loadA(0);
    cpB(0, 0);

    for (int c = 0; c < NCH; c++) {
        const int s = c & 1;
        convA(s);
        if (c + 1 < NCH) loadA((c + 1) * KC);
        CP_WAIT(0);            // B(c) arrived
        __syncthreads();       // A(c) stores + B(c) visible; prior MMA drained
        if (c + 1 < NCH) cpB(c + 1, s ^ 1);   // overlaps MMA(c)

        const uint32_t aHi = base + s * 2 * ABUF;
        const uint32_t aLo = aHi + ABUF;
        const uint32_t bHi = bBase + s * 2 * BBUF;
        const uint32_t bLo = bHi + BBUF;
        #pragma unroll
        for (int kk = 0; kk < 4; kk++) {
            uint32_t a_hi[4], a_lo[4];
            uint32_t aoff = (uint32_t)(((m0 + l16) * APAD + kk * 16 + hi8) * 2);
            ldsm_x4(a_hi, aHi + aoff);
            ldsm_x4(a_lo, aLo + aoff);
            #pragma unroll
            for (int nb = 0; nb < 4; nb++) {
                uint32_t bh[4], bl[4];
                uint32_t boff = (uint32_t)(((kk * 16 + l16) * APAD + nb * 16 + hi8) * 2);
                ldsm_x4_trans(bh, bHi + boff);
                ldsm_x4_trans(bl, bLo + boff);
                mma_bf16(acc[2 * nb + 0], a_hi, bh + 0);
                mma_bf16(acc[2 * nb + 1], a_hi, bh + 2);
                mma_bf16(acc[2 * nb + 0], a_hi, bl + 0);
                mma_bf16(acc[2 * nb + 1], a_hi, bl + 2);
                mma_bf16(acc[2 * nb + 0], a_lo, bh + 0);
                mma_bf16(acc[2 * nb + 1], a_lo, bh + 2);
            }
        }
    }

    // epilogue: split fp32 acc -> bf16 hi/lo global
    const int r = lane >> 2;
    const int cc = (lane & 3) * 2;
    const size_t rA = (size_t)(row0 + m0 + r) * HEAD;
    const size_t rB = (size_t)(row0 + m0 + r + 8) * HEAD;
    #pragma unroll
    for (int j = 0; j < 8; j++) {
        uint32_t h, l;
        split2(acc[j][0] * postmul, acc[j][1] * postmul, h, l);
        *reinterpret_cast<uint32_t*>(&outH[rA + j * 8 + cc]) = h;
        *reinterpret_cast<uint32_t*>(&outL[rA + j * 8 + cc]) = l;
        split2(acc[j][2] * postmul, acc[j][3] * postmul, h, l);
        *reinterpret_cast<uint32_t*>(&outH[rB + j * 8 + cc]) = h;
        *reinterpret_cast<uint32_t*>(&outL[rB + j * 8 + cc]) = l;
    }
}

// ===========================================================================
// Kernel 2: flash attention (validated R6 version, single pass).
// grid = (SEQ/64, BATCH), block = 128.
// ===========================================================================
#define AP 72
#define BUFB (64 * AP * 2)
#define STAGEB (4 * BUFB)
#define ATTN_SMEM (2 * STAGEB + 256)
#define NT (SEQ / 64)

__global__ __launch_bounds__(128) void attn_mma_kernel(
    const int* __restrict__ mask, float* __restrict__ out)
{
    extern __shared__ __align__(16) char smc[];
    const uint32_t smemB = smem_to_u32(smc);
    float* biasS = reinterpret_cast<float*>(smc + 2 * STAGEB);

    const int b  = blockIdx.y;
    const int q0 = blockIdx.x * 64;
    const size_t base = (size_t)b * SEQ * HEAD;

    const int tid  = threadIdx.x;
    const int wid  = tid >> 5;
    const int lane = tid & 31;
    const int l16  = lane & 15;
    const int hi8  = (lane >> 4) << 3;
    const int m0   = wid * 16;
    const int c2   = (lane & 3) * 2;

    const int krow = (lane & 7) + ((lane & 16) >> 1);
    const int hcol = (lane & 8);

    #pragma unroll
    for (int i = 0; i < 4; i++) {
        int idx = tid + i * 128;
        int r = idx >> 3, cq = idx & 7;
        uint4 th = *reinterpret_cast<const uint4*>(g_qh + base + (size_t)(q0 + r) * HEAD + cq * 8);
        uint4 tl = *reinterpret_cast<const uint4*>(g_ql + base + (size_t)(q0 + r) * HEAD + cq * 8);
        *reinterpret_cast<uint4*>(smc + r * 144 + cq * 16)        = th;
        *reinterpret_cast<uint4*>(smc + BUFB + r * 144 + cq * 16) = tl;
    }
    __syncthreads();
    uint32_t qh[4][4], qlr[4][4];
    #pragma unroll
    for (int kh = 0; kh < 4; kh++) {
        uint32_t aoff = (uint32_t)(((m0 + l16) * AP + kh * 16 + hi8) * 2);
        ldsm_x4(qh[kh],  smemB + aoff);
        ldsm_x4(qlr[kh], smemB + BUFB + aoff);
    }
    __syncthreads();

    const __nv_bfloat16* srcs[4] = {g_kh + base, g_kl + base, g_vh + base, g_vl + base};
    {
        #pragma unroll
        for (int i = 0; i < 16; i++) {
            const int buf = i >> 2;
            int rem = tid + (i & 3) * 128;
            int r = rem >> 3, cq = rem & 7;
            cp_async16(smemB + buf * BUFB + r * 144 + cq * 16,
                       srcs[buf] + (size_t)r * HEAD + cq * 8);
        }
        CP_COMMIT();
    }

    const float NEG_INF = __int_as_float(0xff800000);
    float mR0 = NEG_INF, mR1 = NEG_INF, lS0 = 0.f, lS1 = 0.f;
    float o[8][4] = {};

    for (int kt = 0; kt < NT; kt++) {
        const int s = kt & 1;
        const uint32_t stB = smemB + s * STAGEB;

        if (kt + 1 < NT) {
            const int k1 = (kt + 1) * 64;
            const uint32_t st2 = smemB + ((kt + 1) & 1) * STAGEB;
            #pragma unroll
            for (int i = 0; i < 16; i++) {
                const int buf = i >> 2;
                int rem = tid + (i & 3) * 128;
                int r = rem >> 3, cq = rem & 7;
                cp_async16(st2 + buf * BUFB + r * 144 + cq * 16,
                           srcs[buf] + (size_t)(k1 + r) * HEAD + cq * 8);
            }
            CP_COMMIT();
            CP_WAIT(1);
        } else {
            CP_WAIT(0);
        }
        if (tid < 64)
            biasS[tid] = (mask[(size_t)b * SEQ + kt * 64 + tid] != 0) ? 0.f : -1e30f;
        __syncthreads();

        float sF[8][4] = {};
        #pragma unroll
        for (int kh = 0; kh < 4; kh++) {
            #pragma unroll
            for (int nb = 0; nb < 4; nb++) {
                uint32_t bh[4], bl[4];
                uint32_t boff = (uint32_t)(((nb * 16 + krow) * AP + kh * 16 + hcol) * 2);
                ldsm_x4(bh, stB + boff);
                ldsm_x4(bl, stB + BUFB + boff);
                mma_bf16(sF[2 * nb],     qh[kh],  bh);
                mma_bf16(sF[2 * nb + 1], qh[kh],  bh + 2);
                mma_bf16(sF[2 * nb],     qh[kh],  bl);
                mma_bf16(sF[2 * nb + 1], qh[kh],  bl + 2);
                mma_bf16(sF[2 * nb],     qlr[kh], bh);
                mma_bf16(sF[2 * nb + 1], qlr[kh], bh + 2);
            }
        }

        float mx0 = NEG_INF, mx1 = NEG_INF;
        #pragma unroll
        for (int j = 0; j < 8; j++) {
            float2 bv = *reinterpret_cast<float2*>(&biasS[j * 8 + c2]);
            sF[j][0] += bv.x; sF[j][1] += bv.y; sF[j][2] += bv.x; sF[j][3] += bv.y;
            mx0 = fmaxf(mx0, fmaxf(sF[j][0], sF[j][1]));
            mx1 = fmaxf(mx1, fmaxf(sF[j][2], sF[j][3]));
        }
        mx0 = fmaxf(mx0, __shfl_xor_sync(0xffffffffu, mx0, 1));
        mx0 = fmaxf(mx0, __shfl_xor_sync(0xffffffffu, mx0, 2));
        mx1 = fmaxf(mx1, __shfl_xor_sync(0xffffffffu, mx1, 1));
        mx1 = fmaxf(mx1, __shfl_xor_sync(0xffffffffu, mx1, 2));
        float mn0 = fmaxf(mR0, mx0), mn1 = fmaxf(mR1, mx1);
        float a0 = __expf(mR0 - mn0), a1 = __expf(mR1 - mn1);
        float sm0 = 0.f, sm1 = 0.f;
        #pragma unroll
        for (int j = 0; j < 8; j++) {
            sF[j][0] = __expf(sF[j][0] - mn0);
            sF[j][1] = __expf(sF[j][1] - mn0);
            sF[j][2] = __expf(sF[j][2] - mn1);
            sF[j][3] = __expf(sF[j][3] - mn1);
            sm0 += sF[j][0] + sF[j][1];
            sm1 += sF[j][2] + sF[j][3];
        }
        sm0 += __shfl_xor_sync(0xffffffffu, sm0, 1);
        sm0 += __shfl_xor_sync(0xffffffffu, sm0, 2);
        sm1 += __shfl_xor_sync(0xffffffffu, sm1, 1);
        sm1 += __shfl_xor_sync(0xffffffffu, sm1, 2);
        lS0 = lS0 * a0 + sm0; lS1 = lS1 * a1 + sm1;
        mR0 = mn0; mR1 = mn1;
        #pragma unroll
        for (int j = 0; j < 8; j++) {
            o[j][0] *= a0; o[j][1] *= a0; o[j][2] *= a1; o[j][3] *= a1;
        }

        #pragma unroll
        for (int kb = 0; kb < 4; kb++) {
            uint32_t ah[4], al[4];
            split2(sF[2 * kb][0],     sF[2 * kb][1],     ah[0], al[0]);
            split2(sF[2 * kb][2],     sF[2 * kb][3],     ah[1], al[1]);
            split2(sF[2 * kb + 1][0], sF[2 * kb + 1][1], ah[2], al[2]);
            split2(sF[2 * kb + 1][2], sF[2 * kb + 1][3], ah[3], al[3]);
            #pragma unroll
            for (int nb = 0; nb < 4; nb++) {
                uint32_t vh[4], vl[4];
                uint32_t boff = (uint32_t)(((kb * 16 + l16) * AP + nb * 16 + hi8) * 2);
                ldsm_x4_trans(vh, stB + 2 * BUFB + boff);
                ldsm_x4_trans(vl, stB + 3 * BUFB + boff);
                mma_bf16(o[2 * nb],     ah, vh);
                mma_bf16(o[2 * nb + 1], ah, vh + 2);
                mma_bf16(o[2 * nb],     ah, vl);
                mma_bf16(o[2 * nb + 1], ah, vl + 2);
                mma_bf16(o[2 * nb],     al, vh);
                mma_bf16(o[2 * nb + 1], al, vh + 2);
            }
        }
        __syncthreads();
    }

    float inv0 = 1.f / lS0, inv1 = 1.f / lS1;
    int rowA = b * SEQ + q0 + m0 + (lane >> 2);
    #pragma unroll
    for (int j = 0; j < 8; j++) {
        *reinterpret_cast<float2*>(out + (size_t)rowA * HEAD + j * 8 + c2) =
            make_float2(o[j][0] * inv0, o[j][1] * inv0);
        *reinterpret_cast<float2*>(out + (size_t)(rowA + 8) * HEAD + j * 8 + c2) =
            make_float2(o[j][2] * inv1, o[j][3] * inv1);
    }
}

// ---------------------------------------------------------------------------
extern "C" void kernel_launch(void* const* d_in, const int* in_sizes, int n_in,
                              void* d_out, int out_size)
{
    const void* big[3]   = {0, 0, 0};
    const void* small[3] = {0, 0, 0};
    const void* mk = 0;
    int nb = 0, ns = 0;
    for (int i = 0; i < n_in; i++) {
        if (in_sizes[i] == NROWS * DEMB)      { if (nb < 3) big[nb++] = d_in[i]; }
        else if (in_sizes[i] == DEMB * HEAD)  { if (ns < 3) small[ns++] = d_in[i]; }
        else if (in_sizes[i] == BATCH * SEQ)  { mk = d_in[i]; }
    }
    const float* q  = (const float*)big[0];
    const float* k  = (const float*)big[1];
    const float* v  = (const float*)big[2];
    const float* Wq = (const float*)small[0];
    const float* Wk = (const float*)small[1];
    const float* Wv = (const float*)small[2];
    const int*   mask = (const int*)mk;
    float* out = (float*)d_out;

    static bool attr_set = false;
    if (!attr_set) {
        cudaFuncSetAttribute(proj_mma_kernel, cudaFuncAttributeMaxDynamicSharedMemorySize, PROJ_SMEM);
        cudaFuncSetAttribute(attn_mma_kernel, cudaFuncAttributeMaxDynamicSharedMemorySize, ATTN_SMEM);
        attr_set = true;
    }

    wsplit_kernel<<<dim3(64, 3), 256>>>(Wq, Wk, Wv);
    proj_mma_kernel<<<dim3(NROWS / 128, 3), 256, PROJ_SMEM>>>(q, k, v);
    attn_mma_kernel<<<dim3(SEQ / 64, BATCH), 128, ATTN_SMEM>>>(mask, out);
}

// round 9
// speedup vs baseline: 1.3572x; 1.3318x over previous
#include <cuda_runtime.h>
#include <cuda_fp16.h>
#include <cstdint>

// Problem constants (Head_84533546320520)
#define BATCH 8
#define SEQ   2048
#define DEMB  1024
#define HEAD  64
#define NROWS (BATCH * SEQ)   // 16384
#define SCALE 0.125f          // HEAD^-0.5

// fp16 scratch: q split (hi+lo, pre-scaled), k/v single hi
__device__ __half g_qh[NROWS * HEAD];
__device__ __half g_ql[NROWS * HEAD];
__device__ __half g_kh[NROWS * HEAD];
__device__ __half g_vh[NROWS * HEAD];

// Pre-split weights (B-side of proj GEMM): hi + lo
__device__ __half g_wh[3][DEMB * HEAD];
__device__ __half g_wl[3][DEMB * HEAD];

// ===========================================================================
// helpers
// ===========================================================================
__device__ __forceinline__ uint32_t smem_to_u32(const void* p) {
    uint32_t a;
    asm("{ .reg .u64 t; cvta.to.shared.u64 t, %1; cvt.u32.u64 %0, t; }"
        : "=r"(a) : "l"(p));
    return a;
}
__device__ __forceinline__ void ldsm_x4(uint32_t* r, uint32_t addr) {
    asm volatile("ldmatrix.sync.aligned.m8n8.x4.shared.b16 {%0,%1,%2,%3}, [%4];"
        : "=r"(r[0]), "=r"(r[1]), "=r"(r[2]), "=r"(r[3]) : "r"(addr));
}
__device__ __forceinline__ void ldsm_x4_trans(uint32_t* r, uint32_t addr) {
    asm volatile("ldmatrix.sync.aligned.m8n8.x4.trans.shared.b16 {%0,%1,%2,%3}, [%4];"
        : "=r"(r[0]), "=r"(r[1]), "=r"(r[2]), "=r"(r[3]) : "r"(addr));
}
// D += A(16x16 row) * B(16x8 col), fp16 in, f32 accum
__device__ __forceinline__ void mma_f16(float* d, const uint32_t* a, const uint32_t* b) {
    asm volatile(
        "mma.sync.aligned.m16n8k16.row.col.f32.f16.f16.f32 "
        "{%0,%1,%2,%3}, {%4,%5,%6,%7}, {%8,%9}, {%0,%1,%2,%3};"
        : "+f"(d[0]), "+f"(d[1]), "+f"(d[2]), "+f"(d[3])
        : "r"(a[0]), "r"(a[1]), "r"(a[2]), "r"(a[3]), "r"(b[0]), "r"(b[1]));
}
// split two floats into packed fp16x2 hi + residual lo
__device__ __forceinline__ void split2h(float x, float y, uint32_t& h, uint32_t& l) {
    __half2 hb = __float22half2_rn(make_float2(x, y));
    float2 hf = __half22float2(hb);
    __half2 lb = __float22half2_rn(make_float2(x - hf.x, y - hf.y));
    h = *reinterpret_cast<uint32_t*>(&hb);
    l = *reinterpret_cast<uint32_t*>(&lb);
}
__device__ __forceinline__ uint32_t cvt2h(float x, float y) {
    __half2 hb = __float22half2_rn(make_float2(x, y));
    return *reinterpret_cast<uint32_t*>(&hb);
}
__device__ __forceinline__ void cp_async16(uint32_t saddr, const void* gaddr) {
    asm volatile("cp.async.cg.shared.global [%0], [%1], 16;"
        :: "r"(saddr), "l"(gaddr) : "memory");
}
#define CP_COMMIT()  asm volatile("cp.async.commit_group;" ::: "memory")
#define CP_WAIT(n)   asm volatile("cp.async.wait_group %0;" :: "n"(n) : "memory")

// ===========================================================================
// Kernel 0: pre-split W into fp16 hi/lo. grid (64, 3), block 256.
// ===========================================================================
__global__ __launch_bounds__(256) void wsplit_kernel(
    const float* __restrict__ Wq, const float* __restrict__ Wk,
    const float* __restrict__ Wv)
{
    const int which = blockIdx.y;
    const float* __restrict__ W = (which == 0) ? Wq : (which == 1) ? Wk : Wv;
    int idx = blockIdx.x * 256 + threadIdx.x;       // float4 index
    float4 t = reinterpret_cast<const float4*>(W)[idx];
    uint32_t h0, l0, h1, l1;
    split2h(t.x, t.y, h0, l0);
    split2h(t.z, t.w, h1, l1);
    *reinterpret_cast<uint2*>(&g_wh[which][idx * 4]) = make_uint2(h0, h1);
    *reinterpret_cast<uint2*>(&g_wl[which][idx * 4]) = make_uint2(l0, l1);
}

// ===========================================================================
// Kernel 1: projections. A = X single fp16; B = W hi+lo (2-term emulation).
// grid = (NROWS/128, 3), block = 256. Pipelined (A regs + B cp.async).
// ===========================================================================
#define KC 64
#define NCH (DEMB / KC)
#define APAD 72
#define ABUF (128 * APAD * 2)    // 18432 B (single fp16 A tile)
#define BBUF (64 * APAD * 2)     // 9216 B
#define PROJ_SMEM (2 * ABUF + 4 * BBUF)   // 73728 B

__global__ __launch_bounds__(256) void proj_mma_kernel(
    const float* __restrict__ q, const float* __restrict__ k,
    const float* __restrict__ v)
{
    extern __shared__ __align__(16) char smc[];
    const uint32_t base = smem_to_u32(smc);
    const uint32_t bBase = base + 2 * ABUF;

    const int which = blockIdx.y;
    const float* __restrict__ X = (which == 0) ? q : (which == 1) ? k : v;
    const __half* __restrict__ Wh = g_wh[which];
    const __half* __restrict__ Wl = g_wl[which];
    const float postmul = (which == 0) ? SCALE : 1.0f;

    const int tid = threadIdx.x;
    const int wid = tid >> 5;
    const int lane = tid & 31;
    const int l16 = lane & 15;
    const int hi8 = (lane >> 4) << 3;
    const int row0 = blockIdx.x * 128;
    const int m0 = wid * 16;

    float4 aR8[8];
    auto loadA = [&](int k0) {
        #pragma unroll
        for (int i = 0; i < 8; i++) {
            int idx = tid + i * 256;
            int r = idx >> 4, cg = idx & 15;
            aR8[i] = *reinterpret_cast<const float4*>(
                X + (size_t)(row0 + r) * DEMB + k0 + cg * 4);
        }
    };
    auto convA = [&](int s) {
        const uint32_t aB = base + s * ABUF;
        #pragma unroll
        for (int i = 0; i < 8; i++) {
            int idx = tid + i * 256;
            int r = idx >> 4, cg = idx & 15;
            float4 t = aR8[i];
            uint32_t h0 = cvt2h(t.x, t.y);
            uint32_t h1 = cvt2h(t.z, t.w);
            uint32_t off = (uint32_t)(r * APAD + cg * 4) * 2;
            asm volatile("st.shared.v2.b32 [%0], {%1, %2};" :: "r"(aB + off), "r"(h0), "r"(h1) : "memory");
        }
    };
    auto cpB = [&](int c, int s) {
        const uint32_t bHi = bBase + s * 2 * BBUF;
        const uint32_t bLo = bHi + BBUF;
        const int k0 = c * KC;
        #pragma unroll
        for (int i = 0; i < 4; i++) {
            int rem = tid + (i & 1) * 256;     // 0..511
            int r = rem >> 3, cq = rem & 7;
            uint32_t dst = ((i >> 1) ? bLo : bHi) + r * 144 + cq * 16;
            const __half* src = ((i >> 1) ? Wl : Wh) + (size_t)(k0 + r) * HEAD + cq * 8;
            cp_async16(dst, src);
        }
        CP_COMMIT();
    };

    float acc[8][4] = {};

    loadA(0);
    cpB(0, 0);

    for (int c = 0; c < NCH; c++) {
        const int s = c & 1;
        convA(s);
        if (c + 1 < NCH) loadA((c + 1) * KC);
        CP_WAIT(0);
        __syncthreads();
        if (c + 1 < NCH) cpB(c + 1, s ^ 1);

        const uint32_t aB  = base + s * ABUF;
        const uint32_t bHi = bBase + s * 2 * BBUF;
        const uint32_t bLo = bHi + BBUF;
        #pragma unroll
        for (int kk = 0; kk < 4; kk++) {
            uint32_t af[4];
            uint32_t aoff = (uint32_t)(((m0 + l16) * APAD + kk * 16 + hi8) * 2);
            ldsm_x4(af, aB + aoff);
            #pragma unroll
            for (int nb = 0; nb < 4; nb++) {
                uint32_t bh[4], bl[4];
                uint32_t boff = (uint32_t)(((kk * 16 + l16) * APAD + nb * 16 + hi8) * 2);
                ldsm_x4_trans(bh, bHi + boff);
                ldsm_x4_trans(bl, bLo + boff);
                mma_f16(acc[2 * nb + 0], af, bh + 0);
                mma_f16(acc[2 * nb + 1], af, bh + 2);
                mma_f16(acc[2 * nb + 0], af, bl + 0);
                mma_f16(acc[2 * nb + 1], af, bl + 2);
            }
        }
    }

    // epilogue: q -> split hi/lo; k/v -> single hi
    const int r = lane >> 2;
    const int cc = (lane & 3) * 2;
    const size_t rA = (size_t)(row0 + m0 + r) * HEAD;
    const size_t rB = (size_t)(row0 + m0 + r + 8) * HEAD;
    __half* outH = (which == 0) ? g_qh : (which == 1) ? g_kh : g_vh;
    #pragma unroll
    for (int j = 0; j < 8; j++) {
        uint32_t h, l;
        split2h(acc[j][0] * postmul, acc[j][1] * postmul, h, l);
        *reinterpret_cast<uint32_t*>(&outH[rA + j * 8 + cc]) = h;
        if (which == 0) *reinterpret_cast<uint32_t*>(&g_ql[rA + j * 8 + cc]) = l;
        split2h(acc[j][2] * postmul, acc[j][3] * postmul, h, l);
        *reinterpret_cast<uint32_t*>(&outH[rB + j * 8 + cc]) = h;
        if (which == 0) *reinterpret_cast<uint32_t*>(&g_ql[rB + j * 8 + cc]) = l;
    }
}

// ===========================================================================
// Kernel 2: flash attention, fp16 2-term (A-side split only).
// grid = (SEQ/64, BATCH), block = 128. K/V single fp16 in smem.
// ===========================================================================
#define AP 72
#define BUFB (64 * AP * 2)           // 9216 B
#define STAGEB (2 * BUFB)            // Kh + Vh
#define ATTN_SMEM (2 * STAGEB + 256) // 37120 B
#define NT (SEQ / 64)

__global__ __launch_bounds__(128) void attn_mma_kernel(
    const int* __restrict__ mask, float* __restrict__ out)
{
    extern __shared__ __align__(16) char smc[];
    const uint32_t smemB = smem_to_u32(smc);
    float* biasS = reinterpret_cast<float*>(smc + 2 * STAGEB);

    const int b  = blockIdx.y;
    const int q0 = blockIdx.x * 64;
    const size_t base = (size_t)b * SEQ * HEAD;

    const int tid  = threadIdx.x;
    const int wid  = tid >> 5;
    const int lane = tid & 31;
    const int l16  = lane & 15;
    const int hi8  = (lane >> 4) << 3;
    const int m0   = wid * 16;
    const int c2   = (lane & 3) * 2;

    const int krow = (lane & 7) + ((lane & 16) >> 1);
    const int hcol = (lane & 8);

    // stage pre-split Q (hi at 0, lo at BUFB), extract A-frags
    #pragma unroll
    for (int i = 0; i < 4; i++) {
        int idx = tid + i * 128;
        int r = idx >> 3, cq = idx & 7;
        uint4 th = *reinterpret_cast<const uint4*>(g_qh + base + (size_t)(q0 + r) * HEAD + cq * 8);
        uint4 tl = *reinterpret_cast<const uint4*>(g_ql + base + (size_t)(q0 + r) * HEAD + cq * 8);
        *reinterpret_cast<uint4*>(smc + r * 144 + cq * 16)        = th;
        *reinterpret_cast<uint4*>(smc + BUFB + r * 144 + cq * 16) = tl;
    }
    __syncthreads();
    uint32_t qh[4][4], qlr[4][4];
    #pragma unroll
    for (int kh = 0; kh < 4; kh++) {
        uint32_t aoff = (uint32_t)(((m0 + l16) * AP + kh * 16 + hi8) * 2);
        ldsm_x4(qh[kh],  smemB + aoff);
        ldsm_x4(qlr[kh], smemB + BUFB + aoff);
    }
    __syncthreads();

    const __half* srcs[2] = {g_kh + base, g_vh + base};
    {
        #pragma unroll
        for (int i = 0; i < 8; i++) {
            const int buf = i >> 2;
            int rem = tid + (i & 3) * 128;
            int r = rem >> 3, cq = rem & 7;
            cp_async16(smemB + buf * BUFB + r * 144 + cq * 16,
                       srcs[buf] + (size_t)r * HEAD + cq * 8);
        }
        CP_COMMIT();
    }

    const float NEG_INF = __int_as_float(0xff800000);
    float mR0 = NEG_INF, mR1 = NEG_INF, lS0 = 0.f, lS1 = 0.f;
    float o[8][4] = {};

    for (int kt = 0; kt < NT; kt++) {
        const int s = kt & 1;
        const uint32_t stB = smemB + s * STAGEB;

        if (kt + 1 < NT) {
            const int k1 = (kt + 1) * 64;
            const uint32_t st2 = smemB + ((kt + 1) & 1) * STAGEB;
            #pragma unroll
            for (int i = 0; i < 8; i++) {
                const int buf = i >> 2;
                int rem = tid + (i & 3) * 128;
                int r = rem >> 3, cq = rem & 7;
                cp_async16(st2 + buf * BUFB + r * 144 + cq * 16,
                           srcs[buf] + (size_t)(k1 + r) * HEAD + cq * 8);
            }
            CP_COMMIT();
            CP_WAIT(1);
        } else {
            CP_WAIT(0);
        }
        if (tid < 64)
            biasS[tid] = (mask[(size_t)b * SEQ + kt * 64 + tid] != 0) ? 0.f : -1e30f;
        __syncthreads();

        // ---- S = Q @ K^T (Qh·Kh + Ql·Kh) ----
        float sF[8][4] = {};
        #pragma unroll
        for (int kh = 0; kh < 4; kh++) {
            #pragma unroll
            for (int nb = 0; nb < 4; nb++) {
                uint32_t bh[4];
                uint32_t boff = (uint32_t)(((nb * 16 + krow) * AP + kh * 16 + hcol) * 2);
                ldsm_x4(bh, stB + boff);
                mma_f16(sF[2 * nb],     qh[kh],  bh);
                mma_f16(sF[2 * nb + 1], qh[kh],  bh + 2);
                mma_f16(sF[2 * nb],     qlr[kh], bh);
                mma_f16(sF[2 * nb + 1], qlr[kh], bh + 2);
            }
        }

        // ---- online softmax ----
        float mx0 = NEG_INF, mx1 = NEG_INF;
        #pragma unroll
        for (int j = 0; j < 8; j++) {
            float2 bv = *reinterpret_cast<float2*>(&biasS[j * 8 + c2]);
            sF[j][0] += bv.x; sF[j][1] += bv.y; sF[j][2] += bv.x; sF[j][3] += bv.y;
            mx0 = fmaxf(mx0, fmaxf(sF[j][0], sF[j][1]));
            mx1 = fmaxf(mx1, fmaxf(sF[j][2], sF[j][3]));
        }
        mx0 = fmaxf(mx0, __shfl_xor_sync(0xffffffffu, mx0, 1));
        mx0 = fmaxf(mx0, __shfl_xor_sync(0xffffffffu, mx0, 2));
        mx1 = fmaxf(mx1, __shfl_xor_sync(0xffffffffu, mx1, 1));
        mx1 = fmaxf(mx1, __shfl_xor_sync(0xffffffffu, mx1, 2));
        float mn0 = fmaxf(mR0, mx0), mn1 = fmaxf(mR1, mx1);
        float a0 = __expf(mR0 - mn0), a1 = __expf(mR1 - mn1);
        float sm0 = 0.f, sm1 = 0.f;
        #pragma unroll
        for (int j = 0; j < 8; j++) {
            sF[j][0] = __expf(sF[j][0] - mn0);
            sF[j][1] = __expf(sF[j][1] - mn0);
            sF[j][2] = __expf(sF[j][2] - mn1);
            sF[j][3] = __expf(sF[j][3] - mn1);
            sm0 += sF[j][0] + sF[j][1];
            sm1 += sF[j][2] + sF[j][3];
        }
        sm0 += __shfl_xor_sync(0xffffffffu, sm0, 1);
        sm0 += __shfl_xor_sync(0xffffffffu, sm0, 2);
        sm1 += __shfl_xor_sync(0xffffffffu, sm1, 1);
        sm1 += __shfl_xor_sync(0xffffffffu, sm1, 2);
        lS0 = lS0 * a0 + sm0; lS1 = lS1 * a1 + sm1;
        mR0 = mn0; mR1 = mn1;
        #pragma unroll
        for (int j = 0; j < 8; j++) {
            o[j][0] *= a0; o[j][1] *= a0; o[j][2] *= a1; o[j][3] *= a1;
        }

        // ---- O += P @ V  (Ph·Vh + Pl·Vh) ----
        #pragma unroll
        for (int kb = 0; kb < 4; kb++) {
            uint32_t ah[4], al[4];
            split2h(sF[2 * kb][0],     sF[2 * kb][1],     ah[0], al[0]);
            split2h(sF[2 * kb][2],     sF[2 * kb][3],     ah[1], al[1]);
            split2h(sF[2 * kb + 1][0], sF[2 * kb + 1][1], ah[2], al[2]);
            split2h(sF[2 * kb + 1][2], sF[2 * kb + 1][3], ah[3], al[3]);
            #pragma unroll
            for (int nb = 0; nb < 4; nb++) {
                uint32_t vh[4];
                uint32_t boff = (uint32_t)(((kb * 16 + l16) * AP + nb * 16 + hi8) * 2);
                ldsm_x4_trans(vh, stB + BUFB + boff);
                mma_f16(o[2 * nb],     ah, vh);
                mma_f16(o[2 * nb + 1], ah, vh + 2);
                mma_f16(o[2 * nb],     al, vh);
                mma_f16(o[2 * nb + 1], al, vh + 2);
            }
        }
        __syncthreads();
    }

    float inv0 = 1.f / lS0, inv1 = 1.f / lS1;
    int rowA = b * SEQ + q0 + m0 + (lane >> 2);
    #pragma unroll
    for (int j = 0; j < 8; j++) {
        *reinterpret_cast<float2*>(out + (size_t)rowA * HEAD + j * 8 + c2) =
            make_float2(o[j][0] * inv0, o[j][1] * inv0);
        *reinterpret_cast<float2*>(out + (size_t)(rowA + 8) * HEAD + j * 8 + c2) =
            make_float2(o[j][2] * inv1, o[j][3] * inv1);
    }
}

// ---------------------------------------------------------------------------
extern "C" void kernel_launch(void* const* d_in, const int* in_sizes, int n_in,
                              void* d_out, int out_size)
{
    const void* big[3]   = {0, 0, 0};
    const void* small[3] = {0, 0, 0};
    const void* mk = 0;
    int nb = 0, ns = 0;
    for (int i = 0; i < n_in; i++) {
        if (in_sizes[i] == NROWS * DEMB)      { if (nb < 3) big[nb++] = d_in[i]; }
        else if (in_sizes[i] == DEMB * HEAD)  { if (ns < 3) small[ns++] = d_in[i]; }
        else if (in_sizes[i] == BATCH * SEQ)  { mk = d_in[i]; }
    }
    const float* q  = (const float*)big[0];
    const float* k  = (const float*)big[1];
    const float* v  = (const float*)big[2];
    const float* Wq = (const float*)small[0];
    const float* Wk = (const float*)small[1];
    const float* Wv = (const float*)small[2];
    const int*   mask = (const int*)mk;
    float* out = (float*)d_out;

    static bool attr_set = false;
    if (!attr_set) {
        cudaFuncSetAttribute(proj_mma_kernel, cudaFuncAttributeMaxDynamicSharedMemorySize, PROJ_SMEM);
        cudaFuncSetAttribute(attn_mma_kernel, cudaFuncAttributeMaxDynamicSharedMemorySize, ATTN_SMEM);
        attr_set = true;
    }

    wsplit_kernel<<<dim3(64, 3), 256>>>(Wq, Wk, Wv);
    proj_mma_kernel<<<dim3(NROWS / 128, 3), 256, PROJ_SMEM>>>(q, k, v);
    attn_mma_kernel<<<dim3(SEQ / 64, BATCH), 128, ATTN_SMEM>>>(mask, out);
}

// round 10
// speedup vs baseline: 1.4534x; 1.0709x over previous
#include <cuda_runtime.h>
#include <cuda_fp16.h>
#include <cstdint>

// Problem constants (Head_84533546320520)
#define BATCH 8
#define SEQ   2048
#define DEMB  1024
#define HEAD  64
#define NROWS (BATCH * SEQ)   // 16384
#define SCALE 0.125f          // HEAD^-0.5

// fp16 scratch: q split (hi+lo, pre-scaled), k/v single hi
__device__ __half g_qh[NROWS * HEAD];
__device__ __half g_ql[NROWS * HEAD];
__device__ __half g_kh[NROWS * HEAD];
__device__ __half g_vh[NROWS * HEAD];

// Pre-split weights (B-side of proj GEMM): hi + lo
__device__ __half g_wh[3][DEMB * HEAD];
__device__ __half g_wl[3][DEMB * HEAD];

// ===========================================================================
// helpers
// ===========================================================================
__device__ __forceinline__ uint32_t smem_to_u32(const void* p) {
    uint32_t a;
    asm("{ .reg .u64 t; cvta.to.shared.u64 t, %1; cvt.u32.u64 %0, t; }"
        : "=r"(a) : "l"(p));
    return a;
}
__device__ __forceinline__ void ldsm_x4(uint32_t* r, uint32_t addr) {
    asm volatile("ldmatrix.sync.aligned.m8n8.x4.shared.b16 {%0,%1,%2,%3}, [%4];"
        : "=r"(r[0]), "=r"(r[1]), "=r"(r[2]), "=r"(r[3]) : "r"(addr));
}
__device__ __forceinline__ void ldsm_x4_trans(uint32_t* r, uint32_t addr) {
    asm volatile("ldmatrix.sync.aligned.m8n8.x4.trans.shared.b16 {%0,%1,%2,%3}, [%4];"
        : "=r"(r[0]), "=r"(r[1]), "=r"(r[2]), "=r"(r[3]) : "r"(addr));
}
// D += A(16x16 row) * B(16x8 col), fp16 in, f32 accum
__device__ __forceinline__ void mma_f16(float* d, const uint32_t* a, const uint32_t* b) {
    asm volatile(
        "mma.sync.aligned.m16n8k16.row.col.f32.f16.f16.f32 "
        "{%0,%1,%2,%3}, {%4,%5,%6,%7}, {%8,%9}, {%0,%1,%2,%3};"
        : "+f"(d[0]), "+f"(d[1]), "+f"(d[2]), "+f"(d[3])
        : "r"(a[0]), "r"(a[1]), "r"(a[2]), "r"(a[3]), "r"(b[0]), "r"(b[1]));
}
// split two floats into packed fp16x2 hi + residual lo
__device__ __forceinline__ void split2h(float x, float y, uint32_t& h, uint32_t& l) {
    __half2 hb = __float22half2_rn(make_float2(x, y));
    float2 hf = __half22float2(hb);
    __half2 lb = __float22half2_rn(make_float2(x - hf.x, y - hf.y));
    h = *reinterpret_cast<uint32_t*>(&hb);
    l = *reinterpret_cast<uint32_t*>(&lb);
}
__device__ __forceinline__ uint32_t cvt2h(float x, float y) {
    __half2 hb = __float22half2_rn(make_float2(x, y));
    return *reinterpret_cast<uint32_t*>(&hb);
}
__device__ __forceinline__ void cp_async16(uint32_t saddr, const void* gaddr) {
    asm volatile("cp.async.cg.shared.global [%0], [%1], 16;"
        :: "r"(saddr), "l"(gaddr) : "memory");
}
#define CP_COMMIT()  asm volatile("cp.async.commit_group;" ::: "memory")
#define CP_WAIT(n)   asm volatile("cp.async.wait_group %0;" :: "n"(n) : "memory")

// ===========================================================================
// Kernel 0: pre-split W into fp16 hi/lo. grid (64, 3), block 256.
// ===========================================================================
__global__ __launch_bounds__(256) void wsplit_kernel(
    const float* __restrict__ Wq, const float* __restrict__ Wk,
    const float* __restrict__ Wv)
{
    const int which = blockIdx.y;
    const float* __restrict__ W = (which == 0) ? Wq : (which == 1) ? Wk : Wv;
    int idx = blockIdx.x * 256 + threadIdx.x;       // float4 index
    float4 t = reinterpret_cast<const float4*>(W)[idx];
    uint32_t h0, l0, h1, l1;
    split2h(t.x, t.y, h0, l0);
    split2h(t.z, t.w, h1, l1);
    *reinterpret_cast<uint2*>(&g_wh[which][idx * 4]) = make_uint2(h0, h1);
    *reinterpret_cast<uint2*>(&g_wl[which][idx * 4]) = make_uint2(l0, l1);
}

// ===========================================================================
// Kernel 1: projections. A = X single fp16; B = W hi+lo (2-term emulation).
// grid = (NROWS/128, 3), block = 256. Pipelined (A regs + B cp.async).
// ===========================================================================
#define KC 64
#define NCH (DEMB / KC)
#define APAD 72
#define ABUF (128 * APAD * 2)    // 18432 B (single fp16 A tile)
#define BBUF (64 * APAD * 2)     // 9216 B
#define PROJ_SMEM (2 * ABUF + 4 * BBUF)   // 73728 B

__global__ __launch_bounds__(256) void proj_mma_kernel(
    const float* __restrict__ q, const float* __restrict__ k,
    const float* __restrict__ v)
{
    extern __shared__ __align__(16) char smc[];
    const uint32_t base = smem_to_u32(smc);
    const uint32_t bBase = base + 2 * ABUF;

    const int which = blockIdx.y;
    const float* __restrict__ X = (which == 0) ? q : (which == 1) ? k : v;
    const __half* __restrict__ Wh = g_wh[which];
    const __half* __restrict__ Wl = g_wl[which];
    const float postmul = (which == 0) ? SCALE : 1.0f;

    const int tid = threadIdx.x;
    const int wid = tid >> 5;
    const int lane = tid & 31;
    const int l16 = lane & 15;
    const int hi8 = (lane >> 4) << 3;
    const int row0 = blockIdx.x * 128;
    const int m0 = wid * 16;

    float4 aR8[8];
    auto loadA = [&](int k0) {
        #pragma unroll
        for (int i = 0; i < 8; i++) {
            int idx = tid + i * 256;
            int r = idx >> 4, cg = idx & 15;
            aR8[i] = *reinterpret_cast<const float4*>(
                X + (size_t)(row0 + r) * DEMB + k0 + cg * 4);
        }
    };
    auto convA = [&](int s) {
        const uint32_t aB = base + s * ABUF;
        #pragma unroll
        for (int i = 0; i < 8; i++) {
            int idx = tid + i * 256;
            int r = idx >> 4, cg = idx & 15;
            float4 t = aR8[i];
            uint32_t h0 = cvt2h(t.x, t.y);
            uint32_t h1 = cvt2h(t.z, t.w);
            uint32_t off = (uint32_t)(r * APAD + cg * 4) * 2;
            asm volatile("st.shared.v2.b32 [%0], {%1, %2};" :: "r"(aB + off), "r"(h0), "r"(h1) : "memory");
        }
    };
    auto cpB = [&](int c, int s) {
        const uint32_t bHi = bBase + s * 2 * BBUF;
        const uint32_t bLo = bHi + BBUF;
        const int k0 = c * KC;
        #pragma unroll
        for (int i = 0; i < 4; i++) {
            int rem = tid + (i & 1) * 256;     // 0..511
            int r = rem >> 3, cq = rem & 7;
            uint32_t dst = ((i >> 1) ? bLo : bHi) + r * 144 + cq * 16;
            const __half* src = ((i >> 1) ? Wl : Wh) + (size_t)(k0 + r) * HEAD + cq * 8;
            cp_async16(dst, src);
        }
        CP_COMMIT();
    };

    float acc[8][4] = {};

    loadA(0);
    cpB(0, 0);

    for (int c = 0; c < NCH; c++) {
        const int s = c & 1;
        convA(s);
        if (c + 1 < NCH) loadA((c + 1) * KC);
        CP_WAIT(0);
        __syncthreads();
        if (c + 1 < NCH) cpB(c + 1, s ^ 1);

        const uint32_t aB  = base + s * ABUF;
        const uint32_t bHi = bBase + s * 2 * BBUF;
        const uint32_t bLo = bHi + BBUF;
        #pragma unroll
        for (int kk = 0; kk < 4; kk++) {
            uint32_t af[4];
            uint32_t aoff = (uint32_t)(((m0 + l16) * APAD + kk * 16 + hi8) * 2);
            ldsm_x4(af, aB + aoff);
            #pragma unroll
            for (int nb = 0; nb < 4; nb++) {
                uint32_t bh[4], bl[4];
                uint32_t boff = (uint32_t)(((kk * 16 + l16) * APAD + nb * 16 + hi8) * 2);
                ldsm_x4_trans(bh, bHi + boff);
                ldsm_x4_trans(bl, bLo + boff);
                mma_f16(acc[2 * nb + 0], af, bh + 0);
                mma_f16(acc[2 * nb + 1], af, bh + 2);
                mma_f16(acc[2 * nb + 0], af, bl + 0);
                mma_f16(acc[2 * nb + 1], af, bl + 2);
            }
        }
    }

    // epilogue: q -> split hi/lo; k/v -> single hi
    const int r = lane >> 2;
    const int cc = (lane & 3) * 2;
    const size_t rA = (size_t)(row0 + m0 + r) * HEAD;
    const size_t rB = (size_t)(row0 + m0 + r + 8) * HEAD;
    __half* outH = (which == 0) ? g_qh : (which == 1) ? g_kh : g_vh;
    #pragma unroll
    for (int j = 0; j < 8; j++) {
        uint32_t h, l;
        split2h(acc[j][0] * postmul, acc[j][1] * postmul, h, l);
        *reinterpret_cast<uint32_t*>(&outH[rA + j * 8 + cc]) = h;
        if (which == 0) *reinterpret_cast<uint32_t*>(&g_ql[rA + j * 8 + cc]) = l;
        split2h(acc[j][2] * postmul, acc[j][3] * postmul, h, l);
        *reinterpret_cast<uint32_t*>(&outH[rB + j * 8 + cc]) = h;
        if (which == 0) *reinterpret_cast<uint32_t*>(&g_ql[rB + j * 8 + cc]) = l;
    }
}

// ===========================================================================
// Kernel 2: flash attention, fp16. S = 2-term (Qh+Ql)·Kh; PV = 1-term Ph·Vh.
// grid = (SEQ/64, BATCH), block = 128. K/V single fp16 in smem.
// ===========================================================================
#define AP 72
#define BUFB (64 * AP * 2)           // 9216 B
#define STAGEB (2 * BUFB)            // Kh + Vh
#define ATTN_SMEM (2 * STAGEB + 256) // 37120 B
#define NT (SEQ / 64)

__global__ __launch_bounds__(128) void attn_mma_kernel(
    const int* __restrict__ mask, float* __restrict__ out)
{
    extern __shared__ __align__(16) char smc[];
    const uint32_t smemB = smem_to_u32(smc);
    float* biasS = reinterpret_cast<float*>(smc + 2 * STAGEB);

    const int b  = blockIdx.y;
    const int q0 = blockIdx.x * 64;
    const size_t base = (size_t)b * SEQ * HEAD;

    const int tid  = threadIdx.x;
    const int wid  = tid >> 5;
    const int lane = tid & 31;
    const int l16  = lane & 15;
    const int hi8  = (lane >> 4) << 3;
    const int m0   = wid * 16;
    const int c2   = (lane & 3) * 2;

    const int krow = (lane & 7) + ((lane & 16) >> 1);
    const int hcol = (lane & 8);

    // stage pre-split Q (hi at 0, lo at BUFB), extract A-frags
    #pragma unroll
    for (int i = 0; i < 4; i++) {
        int idx = tid + i * 128;
        int r = idx >> 3, cq = idx & 7;
        uint4 th = *reinterpret_cast<const uint4*>(g_qh + base + (size_t)(q0 + r) * HEAD + cq * 8);
        uint4 tl = *reinterpret_cast<const uint4*>(g_ql + base + (size_t)(q0 + r) * HEAD + cq * 8);
        *reinterpret_cast<uint4*>(smc + r * 144 + cq * 16)        = th;
        *reinterpret_cast<uint4*>(smc + BUFB + r * 144 + cq * 16) = tl;
    }
    __syncthreads();
    uint32_t qh[4][4], qlr[4][4];
    #pragma unroll
    for (int kh = 0; kh < 4; kh++) {
        uint32_t aoff = (uint32_t)(((m0 + l16) * AP + kh * 16 + hi8) * 2);
        ldsm_x4(qh[kh],  smemB + aoff);
        ldsm_x4(qlr[kh], smemB + BUFB + aoff);
    }
    __syncthreads();

    const __half* srcs[2] = {g_kh + base, g_vh + base};
    {
        #pragma unroll
        for (int i = 0; i < 8; i++) {
            const int buf = i >> 2;
            int rem = tid + (i & 3) * 128;
            int r = rem >> 3, cq = rem & 7;
            cp_async16(smemB + buf * BUFB + r * 144 + cq * 16,
                       srcs[buf] + (size_t)r * HEAD + cq * 8);
        }
        CP_COMMIT();
    }

    const float NEG_INF = __int_as_float(0xff800000);
    float mR0 = NEG_INF, mR1 = NEG_INF, lS0 = 0.f, lS1 = 0.f;
    float o[8][4] = {};

    for (int kt = 0; kt < NT; kt++) {
        const int s = kt & 1;
        const uint32_t stB = smemB + s * STAGEB;

        if (kt + 1 < NT) {
            const int k1 = (kt + 1) * 64;
            const uint32_t st2 = smemB + ((kt + 1) & 1) * STAGEB;
            #pragma unroll
            for (int i = 0; i < 8; i++) {
                const int buf = i >> 2;
                int rem = tid + (i & 3) * 128;
                int r = rem >> 3, cq = rem & 7;
                cp_async16(st2 + buf * BUFB + r * 144 + cq * 16,
                           srcs[buf] + (size_t)(k1 + r) * HEAD + cq * 8);
            }
            CP_COMMIT();
            CP_WAIT(1);
        } else {
            CP_WAIT(0);
        }
        if (tid < 64)
            biasS[tid] = (mask[(size_t)b * SEQ + kt * 64 + tid] != 0) ? 0.f : -1e30f;
        __syncthreads();

        // ---- S = Q @ K^T (Qh·Kh + Ql·Kh) ----
        float sF[8][4] = {};
        #pragma unroll
        for (int kh = 0; kh < 4; kh++) {
            #pragma unroll
            for (int nb = 0; nb < 4; nb++) {
                uint32_t bh[4];
                uint32_t boff = (uint32_t)(((nb * 16 + krow) * AP + kh * 16 + hcol) * 2);
                ldsm_x4(bh, stB + boff);
                mma_f16(sF[2 * nb],     qh[kh],  bh);
                mma_f16(sF[2 * nb + 1], qh[kh],  bh + 2);
                mma_f16(sF[2 * nb],     qlr[kh], bh);
                mma_f16(sF[2 * nb + 1], qlr[kh], bh + 2);
            }
        }

        // ---- online softmax ----
        float mx0 = NEG_INF, mx1 = NEG_INF;
        #pragma unroll
        for (int j = 0; j < 8; j++) {
            float2 bv = *reinterpret_cast<float2*>(&biasS[j * 8 + c2]);
            sF[j][0] += bv.x; sF[j][1] += bv.y; sF[j][2] += bv.x; sF[j][3] += bv.y;
            mx0 = fmaxf(mx0, fmaxf(sF[j][0], sF[j][1]));
            mx1 = fmaxf(mx1, fmaxf(sF[j][2], sF[j][3]));
        }
        mx0 = fmaxf(mx0, __shfl_xor_sync(0xffffffffu, mx0, 1));
        mx0 = fmaxf(mx0, __shfl_xor_sync(0xffffffffu, mx0, 2));
        mx1 = fmaxf(mx1, __shfl_xor_sync(0xffffffffu, mx1, 1));
        mx1 = fmaxf(mx1, __shfl_xor_sync(0xffffffffu, mx1, 2));
        float mn0 = fmaxf(mR0, mx0), mn1 = fmaxf(mR1, mx1);
        float a0 = __expf(mR0 - mn0), a1 = __expf(mR1 - mn1);
        float sm0 = 0.f, sm1 = 0.f;
        #pragma unroll
        for (int j = 0; j < 8; j++) {
            sF[j][0] = __expf(sF[j][0] - mn0);
            sF[j][1] = __expf(sF[j][1] - mn0);
            sF[j][2] = __expf(sF[j][2] - mn1);
            sF[j][3] = __expf(sF[j][3] - mn1);
            sm0 += sF[j][0] + sF[j][1];
            sm1 += sF[j][2] + sF[j][3];
        }
        sm0 += __shfl_xor_sync(0xffffffffu, sm0, 1);
        sm0 += __shfl_xor_sync(0xffffffffu, sm0, 2);
        sm1 += __shfl_xor_sync(0xffffffffu, sm1, 1);
        sm1 += __shfl_xor_sync(0xffffffffu, sm1, 2);
        lS0 = lS0 * a0 + sm0; lS1 = lS1 * a1 + sm1;
        mR0 = mn0; mR1 = mn1;
        #pragma unroll
        for (int j = 0; j < 8; j++) {
            o[j][0] *= a0; o[j][1] *= a0; o[j][2] *= a1; o[j][3] *= a1;
        }

        // ---- O += P @ V  (single-term Ph·Vh; P in (0,1], no cancellation) ----
        #pragma unroll
        for (int kb = 0; kb < 4; kb++) {
            uint32_t ah[4];
            ah[0] = cvt2h(sF[2 * kb][0],     sF[2 * kb][1]);
            ah[1] = cvt2h(sF[2 * kb][2],     sF[2 * kb][3]);
            ah[2] = cvt2h(sF[2 * kb + 1][0], sF[2 * kb + 1][1]);
            ah[3] = cvt2h(sF[2 * kb + 1][2], sF[2 * kb + 1][3]);
            #pragma unroll
            for (int nb = 0; nb < 4; nb++) {
                uint32_t vh[4];
                uint32_t boff = (uint32_t)(((kb * 16 + l16) * AP + nb * 16 + hi8) * 2);
                ldsm_x4_trans(vh, stB + BUFB + boff);
                mma_f16(o[2 * nb],     ah, vh);
                mma_f16(o[2 * nb + 1], ah, vh + 2);
            }
        }
        __syncthreads();
    }

    float inv0 = 1.f / lS0, inv1 = 1.f / lS1;
    int rowA = b * SEQ + q0 + m0 + (lane >> 2);
    #pragma unroll
    for (int j = 0; j < 8; j++) {
        *reinterpret_cast<float2*>(out + (size_t)rowA * HEAD + j * 8 + c2) =
            make_float2(o[j][0] * inv0, o[j][1] * inv0);
        *reinterpret_cast<float2*>(out + (size_t)(rowA + 8) * HEAD + j * 8 + c2) =
            make_float2(o[j][2] * inv1, o[j][3] * inv1);
    }
}

// ---------------------------------------------------------------------------
extern "C" void kernel_launch(void* const* d_in, const int* in_sizes, int n_in,
                              void* d_out, int out_size)
{
    const void* big[3]   = {0, 0, 0};
    const void* small[3] = {0, 0, 0};
    const void* mk = 0;
    int nb = 0, ns = 0;
    for (int i = 0; i < n_in; i++) {
        if (in_sizes[i] == NROWS * DEMB)      { if (nb < 3) big[nb++] = d_in[i]; }
        else if (in_sizes[i] == DEMB * HEAD)  { if (ns < 3) small[ns++] = d_in[i]; }
        else if (in_sizes[i] == BATCH * SEQ)  { mk = d_in[i]; }
    }
    const float* q  = (const float*)big[0];
    const float* k  = (const float*)big[1];
    const float* v  = (const float*)big[2];
    const float* Wq = (const float*)small[0];
    const float* Wk = (const float*)small[1];
    const float* Wv = (const float*)small[2];
    const int*   mask = (const int*)mk;
    float* out = (float*)d_out;

    static bool attr_set = false;
    if (!attr_set) {
        cudaFuncSetAttribute(proj_mma_kernel, cudaFuncAttributeMaxDynamicSharedMemorySize, PROJ_SMEM);
        cudaFuncSetAttribute(attn_mma_kernel, cudaFuncAttributeMaxDynamicSharedMemorySize, ATTN_SMEM);
        attr_set = true;
    }

    wsplit_kernel<<<dim3(64, 3), 256>>>(Wq, Wk, Wv);
    proj_mma_kernel<<<dim3(NROWS / 128, 3), 256, PROJ_SMEM>>>(q, k, v);
    attn_mma_kernel<<<dim3(SEQ / 64, BATCH), 128, ATTN_SMEM>>>(mask, out);
}